// round 16
// baseline (speedup 1.0000x reference)
#include <cuda_runtime.h>
#include <cuda_bf16.h>
#include <cstdint>

#define BB 8
#define CC 128
#define HWN 4096
#define PC 384
#define NP 49280        // 3*CC*CC + CC
#define LAT 512
#define NSTEP 32
#define EPSV 1e-5f
#define NKS 24          // K = 384 = 24 * 16
#define NCH 12          // 12 chunks of 32 k-rows
#define BROW 68         // padded smem row stride (u32) -> conflict-free LDS

// d_out layout (float32):
//  [0, 98304)               : clip(out[:, :3], -1, 1)
//  [98304, +33*EMB_SLICE)   : out_embs (33,8,128,64,64)
//  then                     : out_raw  (8,3,64,64)
#define OFF_EMBS (BB*3*HWN)
#define EMB_SLICE (BB*CC*HWN)
#define OFF_RAW (OFF_EMBS + 33*EMB_SLICE)

// Linear Y: per (b, k, pix): u32 = (hi bf16 low16) | (lo bf16 high16). 50.3MB
__device__ uint32_t g_ylin[(size_t)BB * PC * HWN];
// A fragment pack: per (b,s,f): 32 lanes x 16 halves = [hi frag 8][lo frag 8]
__device__ __nv_bfloat16 g_wp[(size_t)BB * NKS * 8 * 512];
__device__ float g_params[BB * NP];

// ---------------------------------------------------------------------------
__device__ __forceinline__ void mma16816(float* d, uint4 a, uint32_t b0, uint32_t b1) {
    asm volatile(
        "mma.sync.aligned.m16n8k16.row.col.f32.bf16.bf16.f32 "
        "{%0,%1,%2,%3}, {%4,%5,%6,%7}, {%8,%9}, {%0,%1,%2,%3};"
        : "+f"(d[0]), "+f"(d[1]), "+f"(d[2]), "+f"(d[3])
        : "r"(a.x), "r"(a.y), "r"(a.z), "r"(a.w), "r"(b0), "r"(b1));
}

__device__ __forceinline__ uint32_t fuse_hilo(float v) {
    __nv_bfloat16 h = __float2bfloat16(v);
    __nv_bfloat16 l = __float2bfloat16(v - __bfloat162float(h));
    __nv_bfloat162 p(h, l);
    return *(uint32_t*)&p;   // low16 = hi, high16 = lo
}

__device__ __forceinline__ uint32_t smem_u32(const void* p) {
    uint32_t a;
    asm("{ .reg .u64 t; cvta.to.shared.u64 t, %1; cvt.u32.u64 %0, t; }" : "=r"(a) : "l"(p));
    return a;
}

__device__ __forceinline__ void cp16(uint32_t dst, const void* src) {
    asm volatile("cp.async.cg.shared.global [%0], [%1], 16;" :: "r"(dst), "l"(src));
}
__device__ __forceinline__ void cp_commit() {
    asm volatile("cp.async.commit_group;" ::: "memory");
}
template <int N>
__device__ __forceinline__ void cp_wait() {
    asm volatile("cp.async.wait_group %0;" :: "n"(N) : "memory");
}

// ---------------------------------------------------------------------------
// params[b,p] = lat[b] @ w_dyn[:,p] + b_dyn[p]; weights split hi/lo bf16 into
// the A fragment pack (one-time kernel).
// ---------------------------------------------------------------------------
__global__ void params_kernel(const float* __restrict__ lat,
                              const float* __restrict__ w_dyn,
                              const float* __restrict__ b_dyn) {
    __shared__ float slat[BB * LAT];
    int tid = threadIdx.x;
    for (int i = tid; i < BB * LAT; i += blockDim.x) slat[i] = lat[i];
    __syncthreads();
    int p = blockIdx.x * blockDim.x + tid;
    if (p >= NP) return;
    float acc[BB];
#pragma unroll
    for (int b = 0; b < BB; b++) acc[b] = 0.f;
    for (int k = 0; k < LAT; k++) {
        float w = w_dyn[k * NP + p];
#pragma unroll
        for (int b = 0; b < BB; b++) acc[b] = fmaf(slat[b * LAT + k], w, acc[b]);
    }
    float bd = b_dyn[p];
    bool isw = p < 3 * CC * CC;
    size_t foff = 0;
    if (isw) {
        int m = p / PC, k = p % PC;
        int s = k >> 4, kk = k & 15, f = m >> 4, r = m & 15;
        int lane = (r & 7) * 4 + ((kk & 7) >> 1);
        int reg = (r >> 3) + ((kk >> 3) << 1);
        foff = (size_t)((s * 8 + f) * 512) + lane * 16 + reg * 2 + (kk & 1);
    }
#pragma unroll
    for (int b = 0; b < BB; b++) {
        float v = acc[b] + bd;
        g_params[b * NP + p] = v;
        if (isw) {
            __nv_bfloat16 h = __float2bfloat16(v);
            __nv_bfloat16 l = __float2bfloat16(v - __bfloat162float(h));
            size_t base = (size_t)b * NKS * 8 * 512 + foff;
            g_wp[base] = h;
            g_wp[base + 8] = l;
        }
    }
}

__global__ void seed_kernel(float* __restrict__ out) {
    float* e0 = out + OFF_EMBS;
    for (int i = blockIdx.x * blockDim.x + threadIdx.x; i < EMB_SLICE;
         i += gridDim.x * blockDim.x) {
        int p = i & (HWN - 1);
        e0[i] = (p == (32 * 64 + 32)) ? 1.0f : 0.0f;
    }
}

// ---------------------------------------------------------------------------
// Perception + instance norm -> linear fused hi/lo u32 per pixel, coalesced.
// One block per (b, c); channel c feeds k-rows {c, 128+c, 256+c}.
// ---------------------------------------------------------------------------
__global__ __launch_bounds__(256) void perc_kernel(const float* __restrict__ state) {
    __shared__ __align__(16) float tile[HWN];
    __shared__ float red[6][8];
    __shared__ float tot[6];
    int bc = blockIdx.x;
    int b = bc >> 7, c = bc & 127;
    const float* xp = state + bc * HWN;
    int tid = threadIdx.x;

#pragma unroll
    for (int r = 0; r < 4; r++) {
        int f = tid + 256 * r;
        ((float4*)tile)[f] = ((const float4*)xp)[f];
    }
    __syncthreads();

    float xv[16], gxv[16], gyv[16];
    float s0 = 0, s1 = 0, s2 = 0, s3 = 0, s4 = 0, s5 = 0;
#pragma unroll
    for (int r = 0; r < 4; r++) {
        int f = tid + 256 * r;
        int p0 = f * 4;
        int i = p0 >> 6;
        int j0 = p0 & 63;
#pragma unroll
        for (int q = 0; q < 4; q++) {
            int j = j0 + q;
            float xm1m1 = (i > 0 && j > 0)   ? tile[(i - 1) * 64 + j - 1] : 0.f;
            float xm1c  = (i > 0)            ? tile[(i - 1) * 64 + j]     : 0.f;
            float xm1p1 = (i > 0 && j < 63)  ? tile[(i - 1) * 64 + j + 1] : 0.f;
            float x0m1  = (j > 0)            ? tile[i * 64 + j - 1]       : 0.f;
            float x0p1  = (j < 63)           ? tile[i * 64 + j + 1]       : 0.f;
            float xp1m1 = (i < 63 && j > 0)  ? tile[(i + 1) * 64 + j - 1] : 0.f;
            float xp1c  = (i < 63)           ? tile[(i + 1) * 64 + j]     : 0.f;
            float xp1p1 = (i < 63 && j < 63) ? tile[(i + 1) * 64 + j + 1] : 0.f;
            float xc = tile[i * 64 + j];
            float gx = ((xm1p1 - xm1m1) + 2.f * (x0p1 - x0m1) + (xp1p1 - xp1m1)) * 0.125f;
            float gy = ((xp1m1 - xm1m1) + 2.f * (xp1c - xm1c) + (xp1p1 - xm1p1)) * 0.125f;
            int idx = r * 4 + q;
            xv[idx] = xc; gxv[idx] = gx; gyv[idx] = gy;
            s0 += xc; s1 += xc * xc;
            s2 += gx; s3 += gx * gx;
            s4 += gy; s5 += gy * gy;
        }
    }
    float s[6] = {s0, s1, s2, s3, s4, s5};
#pragma unroll
    for (int o = 16; o > 0; o >>= 1)
#pragma unroll
        for (int q = 0; q < 6; q++) s[q] += __shfl_down_sync(0xffffffffu, s[q], o);
    int warp = tid >> 5, lane = tid & 31;
    if (lane == 0)
#pragma unroll
        for (int q = 0; q < 6; q++) red[q][warp] = s[q];
    __syncthreads();
    if (tid < 6) {
        float t = 0;
#pragma unroll
        for (int w2 = 0; w2 < 8; w2++) t += red[tid][w2];
        tot[tid] = t;
    }
    __syncthreads();
    const float inv = 1.f / 4096.f;
    float mx  = tot[0] * inv;
    float mgx = tot[2] * inv;
    float mgy = tot[4] * inv;
    float rx  = rsqrtf(fmaxf(tot[1] * inv - mx * mx, 0.f) + EPSV);
    float rgx = rsqrtf(fmaxf(tot[3] * inv - mgx * mgx, 0.f) + EPSV);
    float rgy = rsqrtf(fmaxf(tot[5] * inv - mgy * mgy, 0.f) + EPSV);

    uint32_t* lx  = g_ylin + (size_t)(b * PC + c) * HWN;
    uint32_t* lgx = g_ylin + (size_t)(b * PC + CC + c) * HWN;
    uint32_t* lgy = g_ylin + (size_t)(b * PC + 2 * CC + c) * HWN;

#pragma unroll
    for (int r = 0; r < 4; r++) {
        int f = tid + 256 * r;
        int p0 = f * 4;
        int base = r * 4;
        uint4 ox, ogx, ogy;
        ox.x = fuse_hilo((xv[base + 0] - mx) * rx);
        ox.y = fuse_hilo((xv[base + 1] - mx) * rx);
        ox.z = fuse_hilo((xv[base + 2] - mx) * rx);
        ox.w = fuse_hilo((xv[base + 3] - mx) * rx);
        ogx.x = fuse_hilo((gxv[base + 0] - mgx) * rgx);
        ogx.y = fuse_hilo((gxv[base + 1] - mgx) * rgx);
        ogx.z = fuse_hilo((gxv[base + 2] - mgx) * rgx);
        ogx.w = fuse_hilo((gxv[base + 3] - mgx) * rgx);
        ogy.x = fuse_hilo((gyv[base + 0] - mgy) * rgy);
        ogy.y = fuse_hilo((gyv[base + 1] - mgy) * rgy);
        ogy.z = fuse_hilo((gyv[base + 2] - mgy) * rgy);
        ogy.w = fuse_hilo((gyv[base + 3] - mgy) * rgy);
        *(uint4*)(lx + p0) = ox;
        *(uint4*)(lgx + p0) = ogx;
        *(uint4*)(lgy + p0) = ogy;
    }
}

// ---------------------------------------------------------------------------
// HMMA GEMM: cp.async 3-stage ring, 32 k-rows (2 k-steps) per stage ->
// 12 barriers instead of 24. Per k-step: all LDS hoisted, then 3 passes of
// 8 independent mma (acc reuse at distance 8). A register double-buffered.
// ---------------------------------------------------------------------------
__global__ __launch_bounds__(256, 3) void gemm_kernel(const float* __restrict__ lf_ptr,
                                                      const float* __restrict__ prev,
                                                      float* __restrict__ next) {
    __shared__ __align__(16) uint32_t Bs[3][32 * BROW];
    int tid = threadIdx.x;
    int warp = tid >> 5, lane = tid & 31;
    int wm = warp & 3, wn = warp >> 2;
    int b = blockIdx.y, pt = blockIdx.x;

    float acc[2][4][4];
#pragma unroll
    for (int f = 0; f < 2; f++)
#pragma unroll
        for (int g = 0; g < 4; g++)
#pragma unroll
            for (int v = 0; v < 4; v++) acc[f][g][v] = 0.f;

    const uint4* WP = (const uint4*)g_wp;
    size_t abase = ((size_t)b * NKS * 8 + wm * 2) * 64 + lane * 2;

    // cp.async staging: thread t copies rows crow and crow+16 of each chunk
    int crow = tid >> 4, ccol = (tid & 15) * 4;
    const uint32_t* Ysrc = g_ylin + (size_t)b * PC * HWN + pt * 64 + (size_t)crow * HWN + ccol;
    uint32_t dst0[3], dst1[3];
#pragma unroll
    for (int st = 0; st < 3; st++) {
        dst0[st] = smem_u32(&Bs[st][crow * BROW + ccol]);
        dst1[st] = smem_u32(&Bs[st][(crow + 16) * BROW + ccol]);
    }

    // prologue: chunks 0 and 1 in flight (one commit group each)
    cp16(dst0[0], Ysrc);
    cp16(dst1[0], Ysrc + (size_t)16 * HWN);
    cp_commit();
    cp16(dst0[1], Ysrc + (size_t)32 * HWN);
    cp16(dst1[1], Ysrc + (size_t)48 * HWN);
    cp_commit();

    uint4 ah0 = __ldg(&WP[abase]);
    uint4 al0 = __ldg(&WP[abase + 1]);
    uint4 ah1 = __ldg(&WP[abase + 64]);
    uint4 al1 = __ldg(&WP[abase + 65]);

    int q = lane & 3, j = lane >> 2;
    int px0 = wn * 32 + j;

    for (int cs = 0; cs < NCH; cs++) {
        if (cs < NCH - 1) cp_wait<1>();
        else cp_wait<0>();
        __syncthreads();
        // all warps finished reading stage (cs-1)%3 == (cs+2)%3: safe to refill
        if (cs + 2 < NCH) {
            int st = (cs + 2) % 3;
            cp16(dst0[st], Ysrc + (size_t)(cs + 2) * 32 * HWN);
            cp16(dst1[st], Ysrc + (size_t)((cs + 2) * 32 + 16) * HWN);
            cp_commit();
        }

        const uint32_t* S = Bs[cs % 3];
#pragma unroll
        for (int h = 0; h < 2; h++) {
            int ks = cs * 2 + h;
            // prefetch next k-step's A fragments
            uint4 nh0, nl0, nh1, nl1;
            if (ks + 1 < NKS) {
                size_t fb = abase + (size_t)(ks + 1) * 512;
                nh0 = __ldg(&WP[fb]);
                nl0 = __ldg(&WP[fb + 1]);
                nh1 = __ldg(&WP[fb + 64]);
                nl1 = __ldg(&WP[fb + 65]);
            }
            // hoist all LDS for this k-step (4 g-fragments x 4 words)
            const uint32_t* Sq0 = S + (h * 16 + 2 * q) * BROW + px0;
            const uint32_t* Sq8 = Sq0 + 8 * BROW;
            uint32_t bh0[4], bh1[4], bl0[4], bl1[4];
#pragma unroll
            for (int g = 0; g < 4; g++) {
                uint32_t u0 = Sq0[g * 8];
                uint32_t u1 = Sq0[BROW + g * 8];
                uint32_t u2 = Sq8[g * 8];
                uint32_t u3 = Sq8[BROW + g * 8];
                bh0[g] = __byte_perm(u0, u1, 0x5410);
                bh1[g] = __byte_perm(u2, u3, 0x5410);
                bl0[g] = __byte_perm(u0, u1, 0x7632);
                bl1[g] = __byte_perm(u2, u3, 0x7632);
            }
            // pass 1: ah x bh — 8 independent mma
#pragma unroll
            for (int g = 0; g < 4; g++) {
                mma16816(acc[0][g], ah0, bh0[g], bh1[g]);
                mma16816(acc[1][g], ah1, bh0[g], bh1[g]);
            }
            // pass 2: al x bh — reuse of acc at distance 8
#pragma unroll
            for (int g = 0; g < 4; g++) {
                mma16816(acc[0][g], al0, bh0[g], bh1[g]);
                mma16816(acc[1][g], al1, bh0[g], bh1[g]);
            }
            // pass 3: ah x bl
#pragma unroll
            for (int g = 0; g < 4; g++) {
                mma16816(acc[0][g], ah0, bl0[g], bl1[g]);
                mma16816(acc[1][g], ah1, bl0[g], bl1[g]);
            }
            ah0 = nh0; al0 = nl0; ah1 = nh1; al1 = nl1;
        }
    }

    float lf = fminf(fmaxf(__ldg(lf_ptr), 0.001f), 1000.f);
#pragma unroll
    for (int f = 0; f < 2; f++) {
        int r_lo = wm * 32 + f * 16 + (lane >> 2);
        int r_hi = r_lo + 8;
        float b_lo = __ldg(&g_params[b * NP + 3 * CC * CC + r_lo]);
        float b_hi = __ldg(&g_params[b * NP + 3 * CC * CC + r_hi]);
        size_t row_lo = (size_t)(b * CC + r_lo) * HWN;
        size_t row_hi = (size_t)(b * CC + r_hi) * HWN;
#pragma unroll
        for (int g = 0; g < 4; g++) {
            int p = pt * 64 + wn * 32 + g * 8 + (lane & 3) * 2;
            float2 pv0 = __ldg((const float2*)(prev + row_lo + p));
            float2 pv1 = __ldg((const float2*)(prev + row_hi + p));
            float2 o0, o1;
            o0.x = pv0.x + lf * (acc[f][g][0] + b_lo);
            o0.y = pv0.y + lf * (acc[f][g][1] + b_lo);
            o1.x = pv1.x + lf * (acc[f][g][2] + b_hi);
            o1.y = pv1.y + lf * (acc[f][g][3] + b_hi);
            *(float2*)(next + row_lo + p) = o0;
            *(float2*)(next + row_hi + p) = o1;
        }
    }
}

__global__ void final_kernel(float* __restrict__ out) {
    const float* st = out + OFF_EMBS + (size_t)NSTEP * EMB_SLICE;
    int n = BB * 3 * HWN;
    int i = blockIdx.x * blockDim.x + threadIdx.x;
    if (i >= n) return;
    int p = i & (HWN - 1);
    int bc = i >> 12;
    int b = bc / 3, c = bc % 3;
    float v = st[(b * CC + c) * HWN + p];
    out[i] = fminf(fmaxf(v, -1.f), 1.f);
    out[OFF_RAW + i] = v;
}

extern "C" void kernel_launch(void* const* d_in, const int* in_sizes, int n_in,
                              void* d_out, int out_size) {
    const float* lat   = (const float*)d_in[0];
    const float* leak  = (const float*)d_in[1];
    const float* w_dyn = (const float*)d_in[2];
    const float* b_dyn = (const float*)d_in[3];
    float* out = (float*)d_out;

    params_kernel<<<(NP + 127) / 128, 128>>>(lat, w_dyn, b_dyn);
    seed_kernel<<<2048, 256>>>(out);
    for (int s = 0; s < NSTEP; s++) {
        const float* prev = out + OFF_EMBS + (size_t)s * EMB_SLICE;
        float* next = out + OFF_EMBS + (size_t)(s + 1) * EMB_SLICE;
        perc_kernel<<<BB * CC, 256>>>(prev);
        gemm_kernel<<<dim3(64, BB), 256>>>(leak, prev, next);
    }
    final_kernel<<<(BB * 3 * HWN + 255) / 256, 256>>>(out);
}

// round 17
// speedup vs baseline: 1.0465x; 1.0465x over previous
#include <cuda_runtime.h>
#include <cuda_bf16.h>
#include <cstdint>

#define BB 8
#define CC 128
#define HWN 4096
#define PC 384
#define NP 49280        // 3*CC*CC + CC
#define LAT 512
#define NSTEP 32
#define EPSV 1e-5f
#define NKS 24          // K = 384 = 24 * 16
#define NCH 12          // 12 chunks of 32 k-rows
#define NST 4           // cp.async ring stages
#define BROW 36         // padded smem row stride (u32), 32 pix + 4 pad

// d_out layout (float32):
//  [0, 98304)               : clip(out[:, :3], -1, 1)
//  [98304, +33*EMB_SLICE)   : out_embs (33,8,128,64,64)
//  then                     : out_raw  (8,3,64,64)
#define OFF_EMBS (BB*3*HWN)
#define EMB_SLICE (BB*CC*HWN)
#define OFF_RAW (OFF_EMBS + 33*EMB_SLICE)

// Linear Y: per (b, k, pix): u32 = (hi bf16 low16) | (lo bf16 high16). 50.3MB
__device__ uint32_t g_ylin[(size_t)BB * PC * HWN];
// A fragment pack: per (b,s,f): 32 lanes x 16 halves = [hi frag 8][lo frag 8]
__device__ __nv_bfloat16 g_wp[(size_t)BB * NKS * 8 * 512];
__device__ float g_params[BB * NP];

// ---------------------------------------------------------------------------
__device__ __forceinline__ void mma16816(float* d, uint4 a, uint32_t b0, uint32_t b1) {
    asm volatile(
        "mma.sync.aligned.m16n8k16.row.col.f32.bf16.bf16.f32 "
        "{%0,%1,%2,%3}, {%4,%5,%6,%7}, {%8,%9}, {%0,%1,%2,%3};"
        : "+f"(d[0]), "+f"(d[1]), "+f"(d[2]), "+f"(d[3])
        : "r"(a.x), "r"(a.y), "r"(a.z), "r"(a.w), "r"(b0), "r"(b1));
}

__device__ __forceinline__ uint32_t fuse_hilo(float v) {
    __nv_bfloat16 h = __float2bfloat16(v);
    __nv_bfloat16 l = __float2bfloat16(v - __bfloat162float(h));
    __nv_bfloat162 p(h, l);
    return *(uint32_t*)&p;   // low16 = hi, high16 = lo
}

__device__ __forceinline__ uint32_t smem_u32(const void* p) {
    uint32_t a;
    asm("{ .reg .u64 t; cvta.to.shared.u64 t, %1; cvt.u32.u64 %0, t; }" : "=r"(a) : "l"(p));
    return a;
}

__device__ __forceinline__ void cp16(uint32_t dst, const void* src) {
    asm volatile("cp.async.cg.shared.global [%0], [%1], 16;" :: "r"(dst), "l"(src));
}
__device__ __forceinline__ void cp_commit() {
    asm volatile("cp.async.commit_group;" ::: "memory");
}
template <int N>
__device__ __forceinline__ void cp_wait() {
    asm volatile("cp.async.wait_group %0;" :: "n"(N) : "memory");
}

// ---------------------------------------------------------------------------
// params[b,p] = lat[b] @ w_dyn[:,p] + b_dyn[p]; weights split hi/lo bf16 into
// the A fragment pack (one-time kernel).
// ---------------------------------------------------------------------------
__global__ void params_kernel(const float* __restrict__ lat,
                              const float* __restrict__ w_dyn,
                              const float* __restrict__ b_dyn) {
    __shared__ float slat[BB * LAT];
    int tid = threadIdx.x;
    for (int i = tid; i < BB * LAT; i += blockDim.x) slat[i] = lat[i];
    __syncthreads();
    int p = blockIdx.x * blockDim.x + tid;
    if (p >= NP) return;
    float acc[BB];
#pragma unroll
    for (int b = 0; b < BB; b++) acc[b] = 0.f;
    for (int k = 0; k < LAT; k++) {
        float w = w_dyn[k * NP + p];
#pragma unroll
        for (int b = 0; b < BB; b++) acc[b] = fmaf(slat[b * LAT + k], w, acc[b]);
    }
    float bd = b_dyn[p];
    bool isw = p < 3 * CC * CC;
    size_t foff = 0;
    if (isw) {
        int m = p / PC, k = p % PC;
        int s = k >> 4, kk = k & 15, f = m >> 4, r = m & 15;
        int lane = (r & 7) * 4 + ((kk & 7) >> 1);
        int reg = (r >> 3) + ((kk >> 3) << 1);
        foff = (size_t)((s * 8 + f) * 512) + lane * 16 + reg * 2 + (kk & 1);
    }
#pragma unroll
    for (int b = 0; b < BB; b++) {
        float v = acc[b] + bd;
        g_params[b * NP + p] = v;
        if (isw) {
            __nv_bfloat16 h = __float2bfloat16(v);
            __nv_bfloat16 l = __float2bfloat16(v - __bfloat162float(h));
            size_t base = (size_t)b * NKS * 8 * 512 + foff;
            g_wp[base] = h;
            g_wp[base + 8] = l;
        }
    }
}

__global__ void seed_kernel(float* __restrict__ out) {
    float* e0 = out + OFF_EMBS;
    for (int i = blockIdx.x * blockDim.x + threadIdx.x; i < EMB_SLICE;
         i += gridDim.x * blockDim.x) {
        int p = i & (HWN - 1);
        e0[i] = (p == (32 * 64 + 32)) ? 1.0f : 0.0f;
    }
}

// ---------------------------------------------------------------------------
// Perception + instance norm -> linear fused hi/lo u32 per pixel, coalesced.
// One block per (b, c); channel c feeds k-rows {c, 128+c, 256+c}.
// ---------------------------------------------------------------------------
__global__ __launch_bounds__(256) void perc_kernel(const float* __restrict__ state) {
    __shared__ __align__(16) float tile[HWN];
    __shared__ float red[6][8];
    __shared__ float tot[6];
    int bc = blockIdx.x;
    int b = bc >> 7, c = bc & 127;
    const float* xp = state + bc * HWN;
    int tid = threadIdx.x;

#pragma unroll
    for (int r = 0; r < 4; r++) {
        int f = tid + 256 * r;
        ((float4*)tile)[f] = ((const float4*)xp)[f];
    }
    __syncthreads();

    float xv[16], gxv[16], gyv[16];
    float s0 = 0, s1 = 0, s2 = 0, s3 = 0, s4 = 0, s5 = 0;
#pragma unroll
    for (int r = 0; r < 4; r++) {
        int f = tid + 256 * r;
        int p0 = f * 4;
        int i = p0 >> 6;
        int j0 = p0 & 63;
#pragma unroll
        for (int q = 0; q < 4; q++) {
            int j = j0 + q;
            float xm1m1 = (i > 0 && j > 0)   ? tile[(i - 1) * 64 + j - 1] : 0.f;
            float xm1c  = (i > 0)            ? tile[(i - 1) * 64 + j]     : 0.f;
            float xm1p1 = (i > 0 && j < 63)  ? tile[(i - 1) * 64 + j + 1] : 0.f;
            float x0m1  = (j > 0)            ? tile[i * 64 + j - 1]       : 0.f;
            float x0p1  = (j < 63)           ? tile[i * 64 + j + 1]       : 0.f;
            float xp1m1 = (i < 63 && j > 0)  ? tile[(i + 1) * 64 + j - 1] : 0.f;
            float xp1c  = (i < 63)           ? tile[(i + 1) * 64 + j]     : 0.f;
            float xp1p1 = (i < 63 && j < 63) ? tile[(i + 1) * 64 + j + 1] : 0.f;
            float xc = tile[i * 64 + j];
            float gx = ((xm1p1 - xm1m1) + 2.f * (x0p1 - x0m1) + (xp1p1 - xp1m1)) * 0.125f;
            float gy = ((xp1m1 - xm1m1) + 2.f * (xp1c - xm1c) + (xp1p1 - xm1p1)) * 0.125f;
            int idx = r * 4 + q;
            xv[idx] = xc; gxv[idx] = gx; gyv[idx] = gy;
            s0 += xc; s1 += xc * xc;
            s2 += gx; s3 += gx * gx;
            s4 += gy; s5 += gy * gy;
        }
    }
    float s[6] = {s0, s1, s2, s3, s4, s5};
#pragma unroll
    for (int o = 16; o > 0; o >>= 1)
#pragma unroll
        for (int q = 0; q < 6; q++) s[q] += __shfl_down_sync(0xffffffffu, s[q], o);
    int warp = tid >> 5, lane = tid & 31;
    if (lane == 0)
#pragma unroll
        for (int q = 0; q < 6; q++) red[q][warp] = s[q];
    __syncthreads();
    if (tid < 6) {
        float t = 0;
#pragma unroll
        for (int w2 = 0; w2 < 8; w2++) t += red[tid][w2];
        tot[tid] = t;
    }
    __syncthreads();
    const float inv = 1.f / 4096.f;
    float mx  = tot[0] * inv;
    float mgx = tot[2] * inv;
    float mgy = tot[4] * inv;
    float rx  = rsqrtf(fmaxf(tot[1] * inv - mx * mx, 0.f) + EPSV);
    float rgx = rsqrtf(fmaxf(tot[3] * inv - mgx * mgx, 0.f) + EPSV);
    float rgy = rsqrtf(fmaxf(tot[5] * inv - mgy * mgy, 0.f) + EPSV);

    uint32_t* lx  = g_ylin + (size_t)(b * PC + c) * HWN;
    uint32_t* lgx = g_ylin + (size_t)(b * PC + CC + c) * HWN;
    uint32_t* lgy = g_ylin + (size_t)(b * PC + 2 * CC + c) * HWN;

#pragma unroll
    for (int r = 0; r < 4; r++) {
        int f = tid + 256 * r;
        int p0 = f * 4;
        int base = r * 4;
        uint4 ox, ogx, ogy;
        ox.x = fuse_hilo((xv[base + 0] - mx) * rx);
        ox.y = fuse_hilo((xv[base + 1] - mx) * rx);
        ox.z = fuse_hilo((xv[base + 2] - mx) * rx);
        ox.w = fuse_hilo((xv[base + 3] - mx) * rx);
        ogx.x = fuse_hilo((gxv[base + 0] - mgx) * rgx);
        ogx.y = fuse_hilo((gxv[base + 1] - mgx) * rgx);
        ogx.z = fuse_hilo((gxv[base + 2] - mgx) * rgx);
        ogx.w = fuse_hilo((gxv[base + 3] - mgx) * rgx);
        ogy.x = fuse_hilo((gyv[base + 0] - mgy) * rgy);
        ogy.y = fuse_hilo((gyv[base + 1] - mgy) * rgy);
        ogy.z = fuse_hilo((gyv[base + 2] - mgy) * rgy);
        ogy.w = fuse_hilo((gyv[base + 3] - mgy) * rgy);
        *(uint4*)(lx + p0) = ox;
        *(uint4*)(lgx + p0) = ogx;
        *(uint4*)(lgy + p0) = ogy;
    }
}

// ---------------------------------------------------------------------------
// HMMA GEMM: N=32 pixel tiles -> 1024 CTAs (finer wave granularity).
// 4-stage cp.async ring, stage = 32 k-rows x 32 px (4KB). 8 warps (4m x 2n),
// each warp 32m x 16px (g=2). 3-term bf16 split, fp32 accum.
// ---------------------------------------------------------------------------
__global__ __launch_bounds__(256, 3) void gemm_kernel(const float* __restrict__ lf_ptr,
                                                      const float* __restrict__ prev,
                                                      float* __restrict__ next) {
    __shared__ __align__(16) uint32_t Bs[NST][32 * BROW];
    int tid = threadIdx.x;
    int warp = tid >> 5, lane = tid & 31;
    int wm = warp & 3, wn = warp >> 2;
    int b = blockIdx.y, pt = blockIdx.x;   // pt: 32-pixel tile, 0..127

    float acc[2][2][4];
#pragma unroll
    for (int f = 0; f < 2; f++)
#pragma unroll
        for (int g = 0; g < 2; g++)
#pragma unroll
            for (int v = 0; v < 4; v++) acc[f][g][v] = 0.f;

    const uint4* WP = (const uint4*)g_wp;
    size_t abase = ((size_t)b * NKS * 8 + wm * 2) * 64 + lane * 2;

    // staging: thread t copies 16B at (k-row = t>>3, col4 = (t&7)*4) of a chunk
    int crow = tid >> 3, ccol = (tid & 7) * 4;
    const uint32_t* Ysrc = g_ylin + (size_t)b * PC * HWN + pt * 32 + (size_t)crow * HWN + ccol;
    uint32_t dsts[NST];
#pragma unroll
    for (int st = 0; st < NST; st++)
        dsts[st] = smem_u32(&Bs[st][crow * BROW + ccol]);

    // prologue: chunks 0,1,2 in flight (one commit group each)
    cp16(dsts[0], Ysrc);
    cp_commit();
    cp16(dsts[1], Ysrc + (size_t)32 * HWN);
    cp_commit();
    cp16(dsts[2], Ysrc + (size_t)64 * HWN);
    cp_commit();

    uint4 ah0 = __ldg(&WP[abase]);
    uint4 al0 = __ldg(&WP[abase + 1]);
    uint4 ah1 = __ldg(&WP[abase + 64]);
    uint4 al1 = __ldg(&WP[abase + 65]);

    int q = lane & 3, j = lane >> 2;
    int px0 = wn * 16 + j;

    for (int cs = 0; cs < NCH; cs++) {
        if (cs <= NCH - 3) cp_wait<2>();
        else if (cs == NCH - 2) cp_wait<1>();
        else cp_wait<0>();
        __syncthreads();
        // stage (cs+3)%NST == (cs-1)%NST consumed last iteration; all warps
        // crossed the barrier above after consuming it: safe to refill.
        if (cs + 3 < NCH) {
            cp16(dsts[(cs + 3) % NST], Ysrc + (size_t)(cs + 3) * 32 * HWN);
            cp_commit();
        }

        const uint32_t* S = Bs[cs % NST];
#pragma unroll
        for (int h = 0; h < 2; h++) {
            int ks = cs * 2 + h;
            uint4 nh0, nl0, nh1, nl1;
            if (ks + 1 < NKS) {
                size_t fb = abase + (size_t)(ks + 1) * 512;
                nh0 = __ldg(&WP[fb]);
                nl0 = __ldg(&WP[fb + 1]);
                nh1 = __ldg(&WP[fb + 64]);
                nl1 = __ldg(&WP[fb + 65]);
            }
            const uint32_t* Sq0 = S + (h * 16 + 2 * q) * BROW + px0;
            const uint32_t* Sq8 = Sq0 + 8 * BROW;
            uint32_t bh0[2], bh1[2], bl0[2], bl1[2];
#pragma unroll
            for (int g = 0; g < 2; g++) {
                uint32_t u0 = Sq0[g * 8];
                uint32_t u1 = Sq0[BROW + g * 8];
                uint32_t u2 = Sq8[g * 8];
                uint32_t u3 = Sq8[BROW + g * 8];
                bh0[g] = __byte_perm(u0, u1, 0x5410);
                bh1[g] = __byte_perm(u2, u3, 0x5410);
                bl0[g] = __byte_perm(u0, u1, 0x7632);
                bl1[g] = __byte_perm(u2, u3, 0x7632);
            }
#pragma unroll
            for (int g = 0; g < 2; g++) {
                mma16816(acc[0][g], ah0, bh0[g], bh1[g]);
                mma16816(acc[1][g], ah1, bh0[g], bh1[g]);
            }
#pragma unroll
            for (int g = 0; g < 2; g++) {
                mma16816(acc[0][g], al0, bh0[g], bh1[g]);
                mma16816(acc[1][g], al1, bh0[g], bh1[g]);
            }
#pragma unroll
            for (int g = 0; g < 2; g++) {
                mma16816(acc[0][g], ah0, bl0[g], bl1[g]);
                mma16816(acc[1][g], ah1, bl0[g], bl1[g]);
            }
            ah0 = nh0; al0 = nl0; ah1 = nh1; al1 = nl1;
        }
    }

    float lf = fminf(fmaxf(__ldg(lf_ptr), 0.001f), 1000.f);
#pragma unroll
    for (int f = 0; f < 2; f++) {
        int r_lo = wm * 32 + f * 16 + (lane >> 2);
        int r_hi = r_lo + 8;
        float b_lo = __ldg(&g_params[b * NP + 3 * CC * CC + r_lo]);
        float b_hi = __ldg(&g_params[b * NP + 3 * CC * CC + r_hi]);
        size_t row_lo = (size_t)(b * CC + r_lo) * HWN;
        size_t row_hi = (size_t)(b * CC + r_hi) * HWN;
#pragma unroll
        for (int g = 0; g < 2; g++) {
            int p = pt * 32 + wn * 16 + g * 8 + (lane & 3) * 2;
            float2 pv0 = __ldg((const float2*)(prev + row_lo + p));
            float2 pv1 = __ldg((const float2*)(prev + row_hi + p));
            float2 o0, o1;
            o0.x = pv0.x + lf * (acc[f][g][0] + b_lo);
            o0.y = pv0.y + lf * (acc[f][g][1] + b_lo);
            o1.x = pv1.x + lf * (acc[f][g][2] + b_hi);
            o1.y = pv1.y + lf * (acc[f][g][3] + b_hi);
            *(float2*)(next + row_lo + p) = o0;
            *(float2*)(next + row_hi + p) = o1;
        }
    }
}

__global__ void final_kernel(float* __restrict__ out) {
    const float* st = out + OFF_EMBS + (size_t)NSTEP * EMB_SLICE;
    int n = BB * 3 * HWN;
    int i = blockIdx.x * blockDim.x + threadIdx.x;
    if (i >= n) return;
    int p = i & (HWN - 1);
    int bc = i >> 12;
    int b = bc / 3, c = bc % 3;
    float v = st[(b * CC + c) * HWN + p];
    out[i] = fminf(fmaxf(v, -1.f), 1.f);
    out[OFF_RAW + i] = v;
}

extern "C" void kernel_launch(void* const* d_in, const int* in_sizes, int n_in,
                              void* d_out, int out_size) {
    const float* lat   = (const float*)d_in[0];
    const float* leak  = (const float*)d_in[1];
    const float* w_dyn = (const float*)d_in[2];
    const float* b_dyn = (const float*)d_in[3];
    float* out = (float*)d_out;

    params_kernel<<<(NP + 127) / 128, 128>>>(lat, w_dyn, b_dyn);
    seed_kernel<<<2048, 256>>>(out);
    for (int s = 0; s < NSTEP; s++) {
        const float* prev = out + OFF_EMBS + (size_t)s * EMB_SLICE;
        float* next = out + OFF_EMBS + (size_t)(s + 1) * EMB_SLICE;
        perc_kernel<<<BB * CC, 256>>>(prev);
        gemm_kernel<<<dim3(128, BB), 256>>>(leak, prev, next);
    }
    final_kernel<<<(BB * 3 * HWN + 255) / 256, 256>>>(out);
}